// round 16
// baseline (speedup 1.0000x reference)
#include <cuda_runtime.h>
#include <cuda_fp16.h>
#include <cstdint>

#define B_  32
#define T_  512
#define H_  512
#define NB  256
#define MAXL 2048

// packed fp16 activation rows: 64 data halves (32 words) + pad -> 36 words
#define RW       36
#define APB_W    (514 * RW)
#define A_BSTR_W (8 * APB_W)
#define PSTR_W   (32 * A_BSTR_W)
// packed fp16 weights: [pred 3][nt 4][stage 24][n 128][RW]
#define WSLOT_W  (128 * RW)
#define WNT_W    (24 * WSLOT_W)
#define WP_W     (3 * 4 * WNT_W)

// ---------------- scratch ----------------
__device__ __align__(256) uint32_t g_xp [32 * A_BSTR_W];
__device__ __align__(256) uint32_t g_x2p[32 * A_BSTR_W];
__device__ __align__(256) uint32_t g_h1p[3 * PSTR_W];
__device__ __align__(256) uint32_t g_w1p[WP_W];
__device__ __align__(256) uint32_t g_w2p[WP_W];
__device__ __align__(256) uint32_t g_h2 [3 * B_ * T_ * 256];
__device__ float g_x3 [B_ * T_ * H_];
__device__ int   g_cum[B_ * T_];
__device__ int   g_ml [B_];
__device__ int   g_cnt1[384];
__device__ int   g_cnt2[384];

__device__ __forceinline__ uint32_t smem_u32(const void* p) {
    uint32_t a;
    asm("{ .reg .u64 t; cvta.to.shared.u64 t, %1; cvt.u32.u64 %0, t; }" : "=r"(a) : "l"(p));
    return a;
}
__device__ __forceinline__ uint32_t h2pack(float x, float y) {
    __half2 h = __floats2half2_rn(x, y);
    return *reinterpret_cast<uint32_t*>(&h);
}
__device__ __forceinline__ float2 h2unpack(uint32_t u) {
    __half2 h = *reinterpret_cast<__half2*>(&u);
    return __half22float2(h);
}

#define MBAR_INIT(a, n) \
    asm volatile("mbarrier.init.shared.b64 [%0], %1;" :: "r"(a), "r"(n) : "memory")
#define MBAR_EXPECT(a, bytes) \
    asm volatile("mbarrier.arrive.expect_tx.shared.b64 _, [%0], %1;" :: "r"(a), "r"(bytes) : "memory")
#define MBAR_WAIT(a, par) do {                                                   \
    uint32_t _m = (a); uint32_t _p = (par); uint32_t _d;                         \
    asm volatile("{ .reg .pred p;"                                               \
        " mbarrier.try_wait.parity.acquire.cta.shared::cta.b64 p, [%1], %2;"     \
        " selp.b32 %0, 1, 0, p; }" : "=r"(_d) : "r"(_m), "r"(_p) : "memory");    \
    if (!_d) {                                                                   \
        asm volatile("{ .reg .pred P1;"                                          \
            " WL_%=:"                                                            \
            " mbarrier.try_wait.parity.acquire.cta.shared::cta.b64 P1, [%0], %1, 0x989680;" \
            " @P1 bra.uni WD_%=;"                                                \
            " bra.uni WL_%=;"                                                    \
            " WD_%=: }" :: "r"(_m), "r"(_p) : "memory");                         \
    } } while (0)

__device__ __forceinline__ void bulk_ld(uint32_t dst, const void* src,
                                        uint32_t bytes, uint32_t mbar) {
    asm volatile(
        "cp.async.bulk.shared::cluster.global.mbarrier::complete_tx::bytes "
        "[%0], [%1], %2, [%3];"
        :: "r"(dst), "l"(src), "r"(bytes), "r"(mbar) : "memory");
}
#define LDSM_X4(r0, r1, r2, r3, addr) \
    asm volatile("ldmatrix.sync.aligned.m8n8.x4.shared.b16 {%0,%1,%2,%3}, [%4];" \
        : "=r"(r0), "=r"(r1), "=r"(r2), "=r"(r3) : "r"(addr))

// ---------------------------------------------------------------------------
// conv1d(K=3,pad=1) implicit GEMM, fp16 mma m16n8k16 + ldmatrix fragments.
// CTA 128x128, 8 warps 4(M) x 2(N), warp tile 32x64, 2 CTAs/SM.
// Fused "last-CTA" epilogue: LN (conv1) or LN+linear head (conv2).
// ---------------------------------------------------------------------------
#define A_BYTES (130 * RW * 4)
#define B_BYTES (WSLOT_W * 4)
#define SA_OFF  64
#define SB_OFF  (64 + 2 * A_BYTES)
#define CONV_SMEM (SB_OFF + 4 * B_BYTES)

extern __shared__ __align__(128) char csm[];

__global__ void __launch_bounds__(256, 2) conv_fp16_kernel(
    const uint32_t* __restrict__ in0, const uint32_t* __restrict__ in1,
    const uint32_t* __restrict__ in2, const uint32_t* __restrict__ wpk,
    const float* __restrict__ biasAll, uint32_t* __restrict__ outBase,
    int packedOut,
    const float* __restrict__ lnG, const float* __restrict__ lnB,
    const float* __restrict__ lwAll, const float* __restrict__ lbAll,
    float* __restrict__ outPred)
{
    const uint32_t sb = smem_u32(csm);
    const int tid  = threadIdx.x;
    const int lane = tid & 31, wid = tid >> 5;
    const int gr = lane >> 2, tc = lane & 3;
    const int wmm = wid & 3, wnn = wid >> 2;
    const int t0 = blockIdx.x * 128;
    const int n0 = blockIdx.y * 128;
    const int pred = blockIdx.z >> 5;
    const int b    = blockIdx.z & 31;

    const uint32_t* inP = (pred == 0) ? in0 : (pred == 1) ? in1 : in2;
    const uint32_t* aSrc = inP + (size_t)b * A_BSTR_W + (size_t)t0 * RW;
    const uint32_t* wB = wpk + (size_t)(pred * 4 + blockIdx.y) * WNT_W;
    const float* biasP = biasAll + pred * 512;

    if (tid == 0) {
#pragma unroll
        for (int i = 0; i < 6; i++) MBAR_INIT(sb + i * 8, 1);
    }
    __syncthreads();

#define ISSUE_A(c) do {                                                        \
    uint32_t mb = sb + ((c) & 1) * 8;                                          \
    MBAR_EXPECT(mb, A_BYTES);                                                  \
    bulk_ld(sb + SA_OFF + ((c) & 1) * A_BYTES, aSrc + (size_t)(c) * APB_W,     \
            A_BYTES, mb); } while (0)
#define ISSUE_B(s) do {                                                        \
    uint32_t mb = sb + 16 + ((s) & 3) * 8;                                     \
    MBAR_EXPECT(mb, B_BYTES);                                                  \
    bulk_ld(sb + SB_OFF + ((s) & 3) * B_BYTES, wB + (size_t)(s) * WSLOT_W,     \
            B_BYTES, mb); } while (0)

    if (tid == 0) { ISSUE_A(0); ISSUE_B(0); ISSUE_B(1); ISSUE_B(2); }

    const int lm   = lane >> 3;
    const int lrow = lane & 7;
    const int rA = lrow + (lm & 1) * 8;
    const int kA = (lm >> 1) * 4;
    const int nB = (lm >> 1) * 8 + lrow;
    const int kB = (lm & 1) * 4;

    float acc[2][8][4];
#pragma unroll
    for (int mi = 0; mi < 2; mi++)
#pragma unroll
        for (int ni = 0; ni < 8; ni++)
#pragma unroll
            for (int q = 0; q < 4; q++) acc[mi][ni][q] = 0.f;

    int c = 0, tap = 0;
    for (int s = 0; s < 24; ++s) {
        if (tid == 0) {
            if (tap == 0 && c + 1 < 8) ISSUE_A(c + 1);
            if (s + 3 < 24) ISSUE_B(s + 3);
        }
        MBAR_WAIT(sb + 16 + (s & 3) * 8, (s >> 2) & 1);
        if (tap == 0) MBAR_WAIT(sb + (c & 1) * 8, (c >> 1) & 1);

        const uint32_t aAddr0 = sb + SA_OFF + (c & 1) * A_BYTES
                              + ((wmm * 32 + tap + rA) * RW + kA) * 4;
        const uint32_t bAddr0 = sb + SB_OFF + (s & 3) * B_BYTES
                              + ((wnn * 64 + nB) * RW + kB) * 4;
#pragma unroll
        for (int ks = 0; ks < 4; ks++) {
            uint32_t a[2][4], bb[8][2];
#pragma unroll
            for (int mi = 0; mi < 2; mi++)
                LDSM_X4(a[mi][0], a[mi][1], a[mi][2], a[mi][3],
                        aAddr0 + (mi * 16 * RW + ks * 8) * 4);
#pragma unroll
            for (int p = 0; p < 4; p++)
                LDSM_X4(bb[2 * p][0], bb[2 * p][1], bb[2 * p + 1][0], bb[2 * p + 1][1],
                        bAddr0 + (p * 16 * RW + ks * 8) * 4);
#pragma unroll
            for (int mi = 0; mi < 2; mi++)
#pragma unroll
                for (int ni = 0; ni < 8; ni++)
                    asm volatile(
                        "mma.sync.aligned.m16n8k16.row.col.f32.f16.f16.f32 "
                        "{%0,%1,%2,%3}, {%4,%5,%6,%7}, {%8,%9}, {%0,%1,%2,%3};"
                        : "+f"(acc[mi][ni][0]), "+f"(acc[mi][ni][1]),
                          "+f"(acc[mi][ni][2]), "+f"(acc[mi][ni][3])
                        : "r"(a[mi][0]), "r"(a[mi][1]), "r"(a[mi][2]), "r"(a[mi][3]),
                          "r"(bb[ni][0]), "r"(bb[ni][1]));
        }
        __syncthreads();
        if (++tap == 3) { tap = 0; ++c; }
    }

    const int r0 = t0 + wmm * 32 + gr;
    const int c0 = n0 + wnn * 64 + tc * 2;
    if (packedOut) {
        uint32_t* ob = outBase + (size_t)pred * PSTR_W + (size_t)b * A_BSTR_W;
#pragma unroll
        for (int ni = 0; ni < 8; ni++) {
            int col = c0 + ni * 8;
            int ch = col >> 6, wrd = (col & 63) >> 1;
            float b0 = __ldg(&biasP[col]), b1 = __ldg(&biasP[col + 1]);
            uint32_t* cb = ob + (size_t)ch * APB_W + wrd;
#pragma unroll
            for (int mi = 0; mi < 2; mi++) {
                int row = r0 + mi * 16;
                cb[(size_t)(row + 1) * RW] =
                    h2pack(fmaxf(acc[mi][ni][0] + b0, 0.f),
                           fmaxf(acc[mi][ni][1] + b1, 0.f));
                cb[(size_t)(row + 9) * RW] =
                    h2pack(fmaxf(acc[mi][ni][2] + b0, 0.f),
                           fmaxf(acc[mi][ni][3] + b1, 0.f));
            }
        }
        // ---- last-CTA fused LayerNorm over this (pred,b,t0) token block ----
        __threadfence();
        __shared__ int sLast;
        if (tid == 0)
            sLast = atomicAdd(&g_cnt1[blockIdx.z * 4 + blockIdx.x], 1);
        __syncthreads();
        if (sLast == 3) {
            __threadfence();
            const float* g  = lnG + pred * 512;
            const float* bt = lnB + pred * 512;
            for (int i = 0; i < 16; i++) {
                int t = t0 + wid * 16 + i;
                uint32_t* base = ob + (size_t)(t + 1) * RW + lane;
                float2 v[8];
                float s = 0.f, s2 = 0.f;
#pragma unroll
                for (int j = 0; j < 8; j++) {
                    v[j] = h2unpack(base[(size_t)j * APB_W]);
                    s += v[j].x + v[j].y;
                    s2 += v[j].x * v[j].x + v[j].y * v[j].y;
                }
#pragma unroll
                for (int o = 16; o; o >>= 1) {
                    s  += __shfl_xor_sync(0xffffffffu, s,  o);
                    s2 += __shfl_xor_sync(0xffffffffu, s2, o);
                }
                float mean = s * (1.f / 512.f);
                float var  = s2 * (1.f / 512.f) - mean * mean;
                float rs   = rsqrtf(var + 1e-5f);
#pragma unroll
                for (int j = 0; j < 8; j++) {
                    int f = j * 64 + 2 * lane;
                    base[(size_t)j * APB_W] =
                        h2pack((v[j].x - mean) * rs * g[f] + bt[f],
                               (v[j].y - mean) * rs * g[f + 1] + bt[f + 1]);
                }
            }
        }
    } else {
        uint32_t* ob = outBase + (size_t)pred * (B_ * T_ * 256)
                     + (size_t)b * (512 * 256);
#pragma unroll
        for (int ni = 0; ni < 8; ni++) {
            int col = c0 + ni * 8;
            float b0 = __ldg(&biasP[col]), b1 = __ldg(&biasP[col + 1]);
#pragma unroll
            for (int mi = 0; mi < 2; mi++) {
                int row = r0 + mi * 16;
                ob[(size_t)row * 256 + (col >> 1)] =
                    h2pack(fmaxf(acc[mi][ni][0] + b0, 0.f),
                           fmaxf(acc[mi][ni][1] + b1, 0.f));
                ob[(size_t)(row + 8) * 256 + (col >> 1)] =
                    h2pack(fmaxf(acc[mi][ni][2] + b0, 0.f),
                           fmaxf(acc[mi][ni][3] + b1, 0.f));
            }
        }
        // ---- last-CTA fused LN + linear head ----
        __threadfence();
        __shared__ int sLast;
        if (tid == 0)
            sLast = atomicAdd(&g_cnt2[blockIdx.z * 4 + blockIdx.x], 1);
        __syncthreads();
        if (sLast == 3) {
            __threadfence();
            const float* g  = lnG + pred * 512;
            const float* bt = lnB + pred * 512;
            const float* lw = lwAll + pred * 512;
            float lbv = __ldg(&lbAll[pred]);
            for (int i = 0; i < 16; i++) {
                int t = t0 + wid * 16 + i;
                const uint32_t* hr = ob + (size_t)t * 256;
                float2 v[8];
                float s = 0.f, s2 = 0.f;
#pragma unroll
                for (int j = 0; j < 8; j++) {
                    v[j] = h2unpack(hr[lane + 32 * j]);
                    s += v[j].x + v[j].y;
                    s2 += v[j].x * v[j].x + v[j].y * v[j].y;
                }
#pragma unroll
                for (int o = 16; o; o >>= 1) {
                    s  += __shfl_xor_sync(0xffffffffu, s,  o);
                    s2 += __shfl_xor_sync(0xffffffffu, s2, o);
                }
                float mean = s * (1.f / 512.f);
                float var  = s2 * (1.f / 512.f) - mean * mean;
                float rs   = rsqrtf(var + 1e-5f);
                float dot = 0.f;
#pragma unroll
                for (int j = 0; j < 8; j++) {
                    int f = 2 * (lane + 32 * j);
                    dot += ((v[j].x - mean) * rs * g[f] + bt[f]) * lw[f];
                    dot += ((v[j].y - mean) * rs * g[f + 1] + bt[f + 1]) * lw[f + 1];
                }
#pragma unroll
                for (int o = 16; o; o >>= 1)
                    dot += __shfl_xor_sync(0xffffffffu, dot, o);
                if (lane == 0)
                    outPred[(size_t)pred * (B_ * T_) + b * 512 + t] = dot + lbv;
            }
        }
    }
}

__global__ void __launch_bounds__(256) pack_w_kernel(
    const float* __restrict__ w, uint32_t* __restrict__ wp)
{
    int g = blockIdx.x * 256 + threadIdx.x;
    int wd = g % RW;
    int n  = (g / RW) % 128;
    int st = (g / WSLOT_W) % 24;
    int nt = (g / WNT_W) % 4;
    int pr = g / (4 * WNT_W);
    uint32_t o = 0;
    if (wd < 32) {
        int tap = st % 3, ch = st / 3, k = ch * 64 + 2 * wd;
        const float* s = w + ((size_t)((pr * 3 + tap) * 512 + k)) * 512
                       + nt * 128 + n;
        o = h2pack(s[0], s[512]);
    }
    wp[g] = o;
}

// pack-only prep (critical path): xp = fp16(x); x2p = fp16(x+pemb)
__global__ void __launch_bounds__(128) prep_pack_kernel(
    const float* __restrict__ x,
    const float* __restrict__ pitch_t, const float* __restrict__ pbins,
    const float* __restrict__ ptab,
    uint32_t* __restrict__ xp, uint32_t* __restrict__ x2p)
{
    int token = blockIdx.x;
    int b = token >> 9, t = token & 511;
    float pv = pitch_t[token];
    int plo = 0, phi = NB - 1;
    while (plo < phi) { int m = (plo + phi) >> 1; if (pbins[m] < pv) plo = m + 1; else phi = m; }

    int i = threadIdx.x;
    float4 a = ((const float4*)(x + (size_t)token * H_))[i];
    float4 p = ((const float4*)(ptab + (size_t)plo * H_))[i];
    float4 r2 = make_float4(a.x + p.x, a.y + p.y, a.z + p.z, a.w + p.w);

    int ch = i >> 4, w = (i & 15) * 2;
    size_t off = ((size_t)(b * 8 + ch) * 514 + t + 1) * RW + w;
    xp [off]     = h2pack(a.x,  a.y);
    xp [off + 1] = h2pack(a.z,  a.w);
    x2p[off]     = h2pack(r2.x, r2.y);
    x2p[off + 1] = h2pack(r2.z, r2.w);
}

// off-path prep: x3 = x + pemb + eemb (fp32), identical math to before
__global__ void __launch_bounds__(128) prep_x3_kernel(
    const float* __restrict__ x,
    const float* __restrict__ pitch_t, const float* __restrict__ energy_t,
    const float* __restrict__ pbins, const float* __restrict__ ebins,
    const float* __restrict__ ptab, const float* __restrict__ etab,
    float* __restrict__ x3)
{
    int token = blockIdx.x;
    float pv = pitch_t[token], ev = energy_t[token];
    int plo = 0, phi = NB - 1;
    while (plo < phi) { int m = (plo + phi) >> 1; if (pbins[m] < pv) plo = m + 1; else phi = m; }
    int elo = 0, ehi = NB - 1;
    while (elo < ehi) { int m = (elo + ehi) >> 1; if (ebins[m] < ev) elo = m + 1; else ehi = m; }

    int i = threadIdx.x;
    float4 a = ((const float4*)(x + (size_t)token * H_))[i];
    float4 p = ((const float4*)(ptab + (size_t)plo * H_))[i];
    float4 e = ((const float4*)(etab + (size_t)elo * H_))[i];
    float4 r2 = make_float4(a.x + p.x, a.y + p.y, a.z + p.z, a.w + p.w);
    ((float4*)(x3 + (size_t)token * H_))[i] =
        make_float4(r2.x + e.x, r2.y + e.y, r2.z + e.z, r2.w + e.w);
}

// zero halo rows of xp/x2p/h1p AND the epilogue counters
__global__ void __launch_bounds__(256) zero_halo_kernel(
    uint32_t* __restrict__ xp, uint32_t* __restrict__ x2p,
    uint32_t* __restrict__ h1p)
{
    int g = blockIdx.x * 256 + threadIdx.x;
    const int HALO_N = 5 * 512 * RW;          // 92160
    if (g < HALO_N) {
        int wd = g % RW;
        int h  = (g / RW) & 1;
        int ch = (g / (2 * RW)) & 7;
        int b  = (g / (16 * RW)) & 31;
        int buf = g / (512 * RW);
        size_t idx = ((size_t)(b * 8 + ch) * 514 + (h ? 513 : 0)) * RW + wd;
        if (buf == 0)      xp[idx] = 0;
        else if (buf == 1) x2p[idx] = 0;
        else               h1p[(size_t)(buf - 2) * PSTR_W + idx] = 0;
    } else {
        int k = g - HALO_N;
        if (k < 384)       g_cnt1[k] = 0;
        else if (k < 768)  g_cnt2[k - 384] = 0;
    }
}

__global__ void __launch_bounds__(512) cumsum_kernel(
    const int* __restrict__ dur, int* __restrict__ cum,
    int* __restrict__ mellen, float* __restrict__ out_mellen)
{
    __shared__ int s[512];
    int b = blockIdx.x, t = threadIdx.x;
    s[t] = dur[b * T_ + t];
    __syncthreads();
    for (int off = 1; off < 512; off <<= 1) {
        int v = (t >= off) ? s[t - off] : 0;
        __syncthreads();
        s[t] += v;
        __syncthreads();
    }
    cum[b * T_ + t] = s[t];
    if (t == 511) {
        int ml = s[511] < MAXL ? s[511] : MAXL;
        mellen[b] = ml;
        out_mellen[b] = (float)ml;
    }
}

__global__ void __launch_bounds__(128) expand_kernel(
    const float* __restrict__ x3, const int* __restrict__ cum,
    const int* __restrict__ mellen, float* __restrict__ outx,
    float* __restrict__ outmask)
{
    int frame = blockIdx.x, b = blockIdx.y;
    int ml = mellen[b];
    float* orow = outx + ((size_t)b * MAXL + frame) * H_;
    bool masked = frame >= ml;
    if (threadIdx.x == 0) outmask[b * MAXL + frame] = masked ? 1.0f : 0.0f;
    if (masked) {
        ((float4*)orow)[threadIdx.x] = make_float4(0, 0, 0, 0);
        return;
    }
    const int* cb = cum + b * T_;
    int lo = 0, hi = T_;
    while (lo < hi) {
        int mid = (lo + hi) >> 1;
        if (cb[mid] <= frame) lo = mid + 1; else hi = mid;
    }
    if (lo > T_ - 1) lo = T_ - 1;
    ((float4*)orow)[threadIdx.x] =
        ((const float4*)(x3 + ((size_t)b * T_ + lo) * H_))[threadIdx.x];
}

extern "C" void kernel_launch(void* const* d_in, const int* in_sizes, int n_in,
                              void* d_out, int out_size)
{
    const float* x        = (const float*)d_in[0];
    const int*   duration = (const int*)  d_in[2];
    const float* pitch_t  = (const float*)d_in[3];
    const float* energy_t = (const float*)d_in[4];
    const float* c1w = (const float*)d_in[5];
    const float* c1b = (const float*)d_in[6];
    const float* g1  = (const float*)d_in[7];
    const float* b1  = (const float*)d_in[8];
    const float* c2w = (const float*)d_in[9];
    const float* c2b = (const float*)d_in[10];
    const float* g2  = (const float*)d_in[11];
    const float* b2  = (const float*)d_in[12];
    const float* lw  = (const float*)d_in[13];
    const float* lb  = (const float*)d_in[14];
    const float* pbins = (const float*)d_in[15];
    const float* ebins = (const float*)d_in[16];
    const float* ptab  = (const float*)d_in[17];
    const float* etab  = (const float*)d_in[18];

    float* out = (float*)d_out;
    const size_t OFF_LOGDUR = (size_t)B_ * MAXL * H_;
    const size_t OFF_MELLEN = OFF_LOGDUR + 3 * (size_t)B_ * T_;
    const size_t OFF_MASK   = OFF_MELLEN + B_;

    uint32_t *p_xp, *p_x2p, *p_h1p, *p_w1p, *p_w2p, *p_h2;
    float *p_x3;
    int *p_cum, *p_ml;
    cudaGetSymbolAddress((void**)&p_xp,  g_xp);
    cudaGetSymbolAddress((void**)&p_x2p, g_x2p);
    cudaGetSymbolAddress((void**)&p_h1p, g_h1p);
    cudaGetSymbolAddress((void**)&p_w1p, g_w1p);
    cudaGetSymbolAddress((void**)&p_w2p, g_w2p);
    cudaGetSymbolAddress((void**)&p_h2,  g_h2);
    cudaGetSymbolAddress((void**)&p_x3,  g_x3);
    cudaGetSymbolAddress((void**)&p_cum, g_cum);
    cudaGetSymbolAddress((void**)&p_ml,  g_ml);

    cudaFuncSetAttribute(conv_fp16_kernel,
                         cudaFuncAttributeMaxDynamicSharedMemorySize, CONV_SMEM);

    cudaStream_t s1, s2;
    cudaStreamCreateWithFlags(&s1, cudaStreamNonBlocking);
    cudaStreamCreateWithFlags(&s2, cudaStreamNonBlocking);
    cudaEvent_t evStart, evS1, evW2, evExpand;
    cudaEventCreateWithFlags(&evStart,  cudaEventDisableTiming);
    cudaEventCreateWithFlags(&evS1,     cudaEventDisableTiming);
    cudaEventCreateWithFlags(&evW2,     cudaEventDisableTiming);
    cudaEventCreateWithFlags(&evExpand, cudaEventDisableTiming);

    // ---- root fork ----
    cudaEventRecord(evStart, 0);
    cudaStreamWaitEvent(s1, evStart, 0);
    cudaStreamWaitEvent(s2, evStart, 0);

    // s1: conv1 prerequisites (halo/counter zero + w1 pack)
    zero_halo_kernel<<<363, 256, 0, s1>>>(p_xp, p_x2p, p_h1p);
    pack_w_kernel<<<WP_W / 256, 256, 0, s1>>>(c1w, p_w1p);
    cudaEventRecord(evS1, s1);

    // s2: LengthRegulator branch (fully off critical path) + w2 pack
    cumsum_kernel<<<B_, 512, 0, s2>>>(duration, p_cum, p_ml, out + OFF_MELLEN);
    prep_x3_kernel<<<B_ * T_, 128, 0, s2>>>(x, pitch_t, energy_t, pbins, ebins,
                                            ptab, etab, p_x3);
    dim3 egrid(MAXL, B_);
    expand_kernel<<<egrid, 128, 0, s2>>>(p_x3, p_cum, p_ml, out, out + OFF_MASK);
    cudaEventRecord(evExpand, s2);
    pack_w_kernel<<<WP_W / 256, 256, 0, s2>>>(c2w, p_w2p);
    cudaEventRecord(evW2, s2);

    // main: pack-only prep (critical path)
    prep_pack_kernel<<<B_ * T_, 128>>>(x, pitch_t, pbins, ptab, p_xp, p_x2p);

    // main: conv chain with fused LN epilogues
    cudaStreamWaitEvent(0, evS1, 0);
    dim3 cgrid(4, 4, 96);
    conv_fp16_kernel<<<cgrid, 256, CONV_SMEM>>>(
        p_xp, p_xp, p_x2p, p_w1p, c1b, p_h1p, 1,
        g1, b1, nullptr, nullptr, nullptr);
    cudaStreamWaitEvent(0, evW2, 0);
    conv_fp16_kernel<<<cgrid, 256, CONV_SMEM>>>(
        p_h1p, p_h1p + PSTR_W, p_h1p + 2 * (size_t)PSTR_W, p_w2p, c2b, p_h2, 0,
        g2, b2, lw, lb, out + OFF_LOGDUR);

    // join
    cudaStreamWaitEvent(0, evExpand, 0);

    cudaEventDestroy(evStart);
    cudaEventDestroy(evS1);
    cudaEventDestroy(evW2);
    cudaEventDestroy(evExpand);
    cudaStreamDestroy(s1);
    cudaStreamDestroy(s2);
}

// round 17
// speedup vs baseline: 1.5489x; 1.5489x over previous
#include <cuda_runtime.h>
#include <cuda_fp16.h>
#include <cstdint>

#define B_  32
#define T_  512
#define H_  512
#define NB  256
#define MAXL 2048

// packed fp16 activation rows: 64 data halves (32 words) + pad -> 36 words
#define RW       36
#define APB_W    (514 * RW)
#define A_BSTR_W (8 * APB_W)
#define PSTR_W   (32 * A_BSTR_W)
// packed fp16 weights: [pred 3][nt 4][stage 24][n 128][RW]
#define WSLOT_W  (128 * RW)
#define WNT_W    (24 * WSLOT_W)
#define WP_W     (3 * 4 * WNT_W)

// ---------------- scratch ----------------
__device__ __align__(256) uint32_t g_xp [32 * A_BSTR_W];
__device__ __align__(256) uint32_t g_x2p[32 * A_BSTR_W];
__device__ __align__(256) uint32_t g_h1p[3 * PSTR_W];
__device__ __align__(256) uint32_t g_w1p[WP_W];
__device__ __align__(256) uint32_t g_w2p[WP_W];
__device__ __align__(256) uint32_t g_h2 [3 * B_ * T_ * 256];
__device__ float g_x3 [B_ * T_ * H_];
__device__ int   g_cum[B_ * T_];
__device__ int   g_ml [B_];
__device__ int   g_cnt1[384];
__device__ int   g_cnt2[384];

__device__ __forceinline__ uint32_t smem_u32(const void* p) {
    uint32_t a;
    asm("{ .reg .u64 t; cvta.to.shared.u64 t, %1; cvt.u32.u64 %0, t; }" : "=r"(a) : "l"(p));
    return a;
}
__device__ __forceinline__ uint32_t h2pack(float x, float y) {
    __half2 h = __floats2half2_rn(x, y);
    return *reinterpret_cast<uint32_t*>(&h);
}
__device__ __forceinline__ float2 h2unpack(uint32_t u) {
    __half2 h = *reinterpret_cast<__half2*>(&u);
    return __half22float2(h);
}

#define MBAR_INIT(a, n) \
    asm volatile("mbarrier.init.shared.b64 [%0], %1;" :: "r"(a), "r"(n) : "memory")
#define MBAR_EXPECT(a, bytes) \
    asm volatile("mbarrier.arrive.expect_tx.shared.b64 _, [%0], %1;" :: "r"(a), "r"(bytes) : "memory")
#define MBAR_WAIT(a, par) do {                                                   \
    uint32_t _m = (a); uint32_t _p = (par); uint32_t _d;                         \
    asm volatile("{ .reg .pred p;"                                               \
        " mbarrier.try_wait.parity.acquire.cta.shared::cta.b64 p, [%1], %2;"     \
        " selp.b32 %0, 1, 0, p; }" : "=r"(_d) : "r"(_m), "r"(_p) : "memory");    \
    if (!_d) {                                                                   \
        asm volatile("{ .reg .pred P1;"                                          \
            " WL_%=:"                                                            \
            " mbarrier.try_wait.parity.acquire.cta.shared::cta.b64 P1, [%0], %1, 0x989680;" \
            " @P1 bra.uni WD_%=;"                                                \
            " bra.uni WL_%=;"                                                    \
            " WD_%=: }" :: "r"(_m), "r"(_p) : "memory");                         \
    } } while (0)

__device__ __forceinline__ void bulk_ld(uint32_t dst, const void* src,
                                        uint32_t bytes, uint32_t mbar) {
    asm volatile(
        "cp.async.bulk.shared::cluster.global.mbarrier::complete_tx::bytes "
        "[%0], [%1], %2, [%3];"
        :: "r"(dst), "l"(src), "r"(bytes), "r"(mbar) : "memory");
}
#define LDSM_X4(r0, r1, r2, r3, addr) \
    asm volatile("ldmatrix.sync.aligned.m8n8.x4.shared.b16 {%0,%1,%2,%3}, [%4];" \
        : "=r"(r0), "=r"(r1), "=r"(r2), "=r"(r3) : "r"(addr))

// ---------------------------------------------------------------------------
// conv1d(K=3,pad=1) implicit GEMM, fp16 mma m16n8k16 + ldmatrix fragments.
// CTA 128x128, 8 warps 4(M) x 2(N), warp tile 32x64, 2 CTAs/SM.
// Fused "last-CTA" epilogue: LN (conv1) or LN+linear head (conv2).
// ---------------------------------------------------------------------------
#define A_BYTES (130 * RW * 4)
#define B_BYTES (WSLOT_W * 4)
#define SA_OFF  64
#define SB_OFF  (64 + 2 * A_BYTES)
#define CONV_SMEM (SB_OFF + 4 * B_BYTES)

extern __shared__ __align__(128) char csm[];

__global__ void __launch_bounds__(256, 2) conv_fp16_kernel(
    const uint32_t* __restrict__ in0, const uint32_t* __restrict__ in1,
    const uint32_t* __restrict__ in2, const uint32_t* __restrict__ wpk,
    const float* __restrict__ biasAll, uint32_t* __restrict__ outBase,
    int packedOut,
    const float* __restrict__ lnG, const float* __restrict__ lnB,
    const float* __restrict__ lwAll, const float* __restrict__ lbAll,
    float* __restrict__ outPred)
{
    const uint32_t sb = smem_u32(csm);
    const int tid  = threadIdx.x;
    const int lane = tid & 31, wid = tid >> 5;
    const int gr = lane >> 2, tc = lane & 3;
    const int wmm = wid & 3, wnn = wid >> 2;
    const int t0 = blockIdx.x * 128;
    const int n0 = blockIdx.y * 128;
    const int pred = blockIdx.z >> 5;
    const int b    = blockIdx.z & 31;

    const uint32_t* inP = (pred == 0) ? in0 : (pred == 1) ? in1 : in2;
    const uint32_t* aSrc = inP + (size_t)b * A_BSTR_W + (size_t)t0 * RW;
    const uint32_t* wB = wpk + (size_t)(pred * 4 + blockIdx.y) * WNT_W;
    const float* biasP = biasAll + pred * 512;

    if (tid == 0) {
#pragma unroll
        for (int i = 0; i < 6; i++) MBAR_INIT(sb + i * 8, 1);
    }
    __syncthreads();

#define ISSUE_A(c) do {                                                        \
    uint32_t mb = sb + ((c) & 1) * 8;                                          \
    MBAR_EXPECT(mb, A_BYTES);                                                  \
    bulk_ld(sb + SA_OFF + ((c) & 1) * A_BYTES, aSrc + (size_t)(c) * APB_W,     \
            A_BYTES, mb); } while (0)
#define ISSUE_B(s) do {                                                        \
    uint32_t mb = sb + 16 + ((s) & 3) * 8;                                     \
    MBAR_EXPECT(mb, B_BYTES);                                                  \
    bulk_ld(sb + SB_OFF + ((s) & 3) * B_BYTES, wB + (size_t)(s) * WSLOT_W,     \
            B_BYTES, mb); } while (0)

    if (tid == 0) { ISSUE_A(0); ISSUE_B(0); ISSUE_B(1); ISSUE_B(2); }

    const int lm   = lane >> 3;
    const int lrow = lane & 7;
    const int rA = lrow + (lm & 1) * 8;
    const int kA = (lm >> 1) * 4;
    const int nB = (lm >> 1) * 8 + lrow;
    const int kB = (lm & 1) * 4;

    float acc[2][8][4];
#pragma unroll
    for (int mi = 0; mi < 2; mi++)
#pragma unroll
        for (int ni = 0; ni < 8; ni++)
#pragma unroll
            for (int q = 0; q < 4; q++) acc[mi][ni][q] = 0.f;

    int c = 0, tap = 0;
    for (int s = 0; s < 24; ++s) {
        if (tid == 0) {
            if (tap == 0 && c + 1 < 8) ISSUE_A(c + 1);
            if (s + 3 < 24) ISSUE_B(s + 3);
        }
        MBAR_WAIT(sb + 16 + (s & 3) * 8, (s >> 2) & 1);
        if (tap == 0) MBAR_WAIT(sb + (c & 1) * 8, (c >> 1) & 1);

        const uint32_t aAddr0 = sb + SA_OFF + (c & 1) * A_BYTES
                              + ((wmm * 32 + tap + rA) * RW + kA) * 4;
        const uint32_t bAddr0 = sb + SB_OFF + (s & 3) * B_BYTES
                              + ((wnn * 64 + nB) * RW + kB) * 4;
#pragma unroll
        for (int ks = 0; ks < 4; ks++) {
            uint32_t a[2][4], bb[8][2];
#pragma unroll
            for (int mi = 0; mi < 2; mi++)
                LDSM_X4(a[mi][0], a[mi][1], a[mi][2], a[mi][3],
                        aAddr0 + (mi * 16 * RW + ks * 8) * 4);
#pragma unroll
            for (int p = 0; p < 4; p++)
                LDSM_X4(bb[2 * p][0], bb[2 * p][1], bb[2 * p + 1][0], bb[2 * p + 1][1],
                        bAddr0 + (p * 16 * RW + ks * 8) * 4);
#pragma unroll
            for (int mi = 0; mi < 2; mi++)
#pragma unroll
                for (int ni = 0; ni < 8; ni++)
                    asm volatile(
                        "mma.sync.aligned.m16n8k16.row.col.f32.f16.f16.f32 "
                        "{%0,%1,%2,%3}, {%4,%5,%6,%7}, {%8,%9}, {%0,%1,%2,%3};"
                        : "+f"(acc[mi][ni][0]), "+f"(acc[mi][ni][1]),
                          "+f"(acc[mi][ni][2]), "+f"(acc[mi][ni][3])
                        : "r"(a[mi][0]), "r"(a[mi][1]), "r"(a[mi][2]), "r"(a[mi][3]),
                          "r"(bb[ni][0]), "r"(bb[ni][1]));
        }
        __syncthreads();
        if (++tap == 3) { tap = 0; ++c; }
    }

    const int r0 = t0 + wmm * 32 + gr;
    const int c0 = n0 + wnn * 64 + tc * 2;
    if (packedOut) {
        uint32_t* ob = outBase + (size_t)pred * PSTR_W + (size_t)b * A_BSTR_W;
#pragma unroll
        for (int ni = 0; ni < 8; ni++) {
            int col = c0 + ni * 8;
            int ch = col >> 6, wrd = (col & 63) >> 1;
            float b0 = __ldg(&biasP[col]), b1 = __ldg(&biasP[col + 1]);
            uint32_t* cb = ob + (size_t)ch * APB_W + wrd;
#pragma unroll
            for (int mi = 0; mi < 2; mi++) {
                int row = r0 + mi * 16;
                cb[(size_t)(row + 1) * RW] =
                    h2pack(fmaxf(acc[mi][ni][0] + b0, 0.f),
                           fmaxf(acc[mi][ni][1] + b1, 0.f));
                cb[(size_t)(row + 9) * RW] =
                    h2pack(fmaxf(acc[mi][ni][2] + b0, 0.f),
                           fmaxf(acc[mi][ni][3] + b1, 0.f));
            }
        }
        // ---- last-CTA fused LayerNorm over this (pred,b,t0) token block ----
        __threadfence();
        __shared__ int sLast;
        if (tid == 0)
            sLast = atomicAdd(&g_cnt1[blockIdx.z * 4 + blockIdx.x], 1);
        __syncthreads();
        if (sLast == 3) {
            __threadfence();
            const float* g  = lnG + pred * 512;
            const float* bt = lnB + pred * 512;
            for (int i = 0; i < 16; i++) {
                int t = t0 + wid * 16 + i;
                uint32_t* base = ob + (size_t)(t + 1) * RW + lane;
                float2 v[8];
                float s = 0.f, s2 = 0.f;
#pragma unroll
                for (int j = 0; j < 8; j++) {
                    v[j] = h2unpack(base[(size_t)j * APB_W]);
                    s += v[j].x + v[j].y;
                    s2 += v[j].x * v[j].x + v[j].y * v[j].y;
                }
#pragma unroll
                for (int o = 16; o; o >>= 1) {
                    s  += __shfl_xor_sync(0xffffffffu, s,  o);
                    s2 += __shfl_xor_sync(0xffffffffu, s2, o);
                }
                float mean = s * (1.f / 512.f);
                float var  = s2 * (1.f / 512.f) - mean * mean;
                float rs   = rsqrtf(var + 1e-5f);
#pragma unroll
                for (int j = 0; j < 8; j++) {
                    int f = j * 64 + 2 * lane;
                    base[(size_t)j * APB_W] =
                        h2pack((v[j].x - mean) * rs * g[f] + bt[f],
                               (v[j].y - mean) * rs * g[f + 1] + bt[f + 1]);
                }
            }
        }
    } else {
        uint32_t* ob = outBase + (size_t)pred * (B_ * T_ * 256)
                     + (size_t)b * (512 * 256);
#pragma unroll
        for (int ni = 0; ni < 8; ni++) {
            int col = c0 + ni * 8;
            float b0 = __ldg(&biasP[col]), b1 = __ldg(&biasP[col + 1]);
#pragma unroll
            for (int mi = 0; mi < 2; mi++) {
                int row = r0 + mi * 16;
                ob[(size_t)row * 256 + (col >> 1)] =
                    h2pack(fmaxf(acc[mi][ni][0] + b0, 0.f),
                           fmaxf(acc[mi][ni][1] + b1, 0.f));
                ob[(size_t)(row + 8) * 256 + (col >> 1)] =
                    h2pack(fmaxf(acc[mi][ni][2] + b0, 0.f),
                           fmaxf(acc[mi][ni][3] + b1, 0.f));
            }
        }
        // ---- last-CTA fused LN + linear head ----
        __threadfence();
        __shared__ int sLast;
        if (tid == 0)
            sLast = atomicAdd(&g_cnt2[blockIdx.z * 4 + blockIdx.x], 1);
        __syncthreads();
        if (sLast == 3) {
            __threadfence();
            const float* g  = lnG + pred * 512;
            const float* bt = lnB + pred * 512;
            const float* lw = lwAll + pred * 512;
            float lbv = __ldg(&lbAll[pred]);
            for (int i = 0; i < 16; i++) {
                int t = t0 + wid * 16 + i;
                const uint32_t* hr = ob + (size_t)t * 256;
                float2 v[8];
                float s = 0.f, s2 = 0.f;
#pragma unroll
                for (int j = 0; j < 8; j++) {
                    v[j] = h2unpack(hr[lane + 32 * j]);
                    s += v[j].x + v[j].y;
                    s2 += v[j].x * v[j].x + v[j].y * v[j].y;
                }
#pragma unroll
                for (int o = 16; o; o >>= 1) {
                    s  += __shfl_xor_sync(0xffffffffu, s,  o);
                    s2 += __shfl_xor_sync(0xffffffffu, s2, o);
                }
                float mean = s * (1.f / 512.f);
                float var  = s2 * (1.f / 512.f) - mean * mean;
                float rs   = rsqrtf(var + 1e-5f);
                float dot = 0.f;
#pragma unroll
                for (int j = 0; j < 8; j++) {
                    int f = 2 * (lane + 32 * j);
                    dot += ((v[j].x - mean) * rs * g[f] + bt[f]) * lw[f];
                    dot += ((v[j].y - mean) * rs * g[f + 1] + bt[f + 1]) * lw[f + 1];
                }
#pragma unroll
                for (int o = 16; o; o >>= 1)
                    dot += __shfl_xor_sync(0xffffffffu, dot, o);
                if (lane == 0)
                    outPred[(size_t)pred * (B_ * T_) + b * 512 + t] = dot + lbv;
            }
        }
    }
}

__global__ void __launch_bounds__(256) pack_w_kernel(
    const float* __restrict__ w, uint32_t* __restrict__ wp)
{
    int g = blockIdx.x * 256 + threadIdx.x;
    int wd = g % RW;
    int n  = (g / RW) % 128;
    int st = (g / WSLOT_W) % 24;
    int nt = (g / WNT_W) % 4;
    int pr = g / (4 * WNT_W);
    uint32_t o = 0;
    if (wd < 32) {
        int tap = st % 3, ch = st / 3, k = ch * 64 + 2 * wd;
        const float* s = w + ((size_t)((pr * 3 + tap) * 512 + k)) * 512
                       + nt * 128 + n;
        o = h2pack(s[0], s[512]);
    }
    wp[g] = o;
}

__global__ void __launch_bounds__(128) prep_x_kernel(
    const float* __restrict__ x,
    const float* __restrict__ pitch_t, const float* __restrict__ energy_t,
    const float* __restrict__ pbins, const float* __restrict__ ebins,
    const float* __restrict__ ptab, const float* __restrict__ etab,
    uint32_t* __restrict__ xp, uint32_t* __restrict__ x2p,
    float* __restrict__ x3)
{
    int token = blockIdx.x;
    int b = token >> 9, t = token & 511;
    float pv = pitch_t[token], ev = energy_t[token];
    int plo = 0, phi = NB - 1;
    while (plo < phi) { int m = (plo + phi) >> 1; if (pbins[m] < pv) plo = m + 1; else phi = m; }
    int elo = 0, ehi = NB - 1;
    while (elo < ehi) { int m = (elo + ehi) >> 1; if (ebins[m] < ev) elo = m + 1; else ehi = m; }

    int i = threadIdx.x;
    float4 a = ((const float4*)(x + (size_t)token * H_))[i];
    float4 p = ((const float4*)(ptab + (size_t)plo * H_))[i];
    float4 e = ((const float4*)(etab + (size_t)elo * H_))[i];
    float4 r2 = make_float4(a.x + p.x, a.y + p.y, a.z + p.z, a.w + p.w);
    ((float4*)(x3 + (size_t)token * H_))[i] =
        make_float4(r2.x + e.x, r2.y + e.y, r2.z + e.z, r2.w + e.w);

    int ch = i >> 4, w = (i & 15) * 2;
    size_t off = ((size_t)(b * 8 + ch) * 514 + t + 1) * RW + w;
    xp [off]     = h2pack(a.x,  a.y);
    xp [off + 1] = h2pack(a.z,  a.w);
    x2p[off]     = h2pack(r2.x, r2.y);
    x2p[off + 1] = h2pack(r2.z, r2.w);
}

// zero halo rows of xp/x2p/h1p AND the epilogue counters
__global__ void __launch_bounds__(256) zero_halo_kernel(
    uint32_t* __restrict__ xp, uint32_t* __restrict__ x2p,
    uint32_t* __restrict__ h1p)
{
    int g = blockIdx.x * 256 + threadIdx.x;
    const int HALO_N = 5 * 512 * RW;          // 92160
    if (g < HALO_N) {
        int wd = g % RW;
        int h  = (g / RW) & 1;
        int ch = (g / (2 * RW)) & 7;
        int b  = (g / (16 * RW)) & 31;
        int buf = g / (512 * RW);
        size_t idx = ((size_t)(b * 8 + ch) * 514 + (h ? 513 : 0)) * RW + wd;
        if (buf == 0)      xp[idx] = 0;
        else if (buf == 1) x2p[idx] = 0;
        else               h1p[(size_t)(buf - 2) * PSTR_W + idx] = 0;
    } else {
        int k = g - HALO_N;
        if (k < 384)       g_cnt1[k] = 0;
        else if (k < 768)  g_cnt2[k - 384] = 0;
    }
}

__global__ void __launch_bounds__(512) cumsum_kernel(
    const int* __restrict__ dur, int* __restrict__ cum,
    int* __restrict__ mellen, float* __restrict__ out_mellen)
{
    __shared__ int s[512];
    int b = blockIdx.x, t = threadIdx.x;
    s[t] = dur[b * T_ + t];
    __syncthreads();
    for (int off = 1; off < 512; off <<= 1) {
        int v = (t >= off) ? s[t - off] : 0;
        __syncthreads();
        s[t] += v;
        __syncthreads();
    }
    cum[b * T_ + t] = s[t];
    if (t == 511) {
        int ml = s[511] < MAXL ? s[511] : MAXL;
        mellen[b] = ml;
        out_mellen[b] = (float)ml;
    }
}

__global__ void __launch_bounds__(128) expand_kernel(
    const float* __restrict__ x3, const int* __restrict__ cum,
    const int* __restrict__ mellen, float* __restrict__ outx,
    float* __restrict__ outmask)
{
    int frame = blockIdx.x, b = blockIdx.y;
    int ml = mellen[b];
    float* orow = outx + ((size_t)b * MAXL + frame) * H_;
    bool masked = frame >= ml;
    if (threadIdx.x == 0) outmask[b * MAXL + frame] = masked ? 1.0f : 0.0f;
    if (masked) {
        ((float4*)orow)[threadIdx.x] = make_float4(0, 0, 0, 0);
        return;
    }
    const int* cb = cum + b * T_;
    int lo = 0, hi = T_;
    while (lo < hi) {
        int mid = (lo + hi) >> 1;
        if (cb[mid] <= frame) lo = mid + 1; else hi = mid;
    }
    if (lo > T_ - 1) lo = T_ - 1;
    ((float4*)orow)[threadIdx.x] =
        ((const float4*)(x3 + ((size_t)b * T_ + lo) * H_))[threadIdx.x];
}

extern "C" void kernel_launch(void* const* d_in, const int* in_sizes, int n_in,
                              void* d_out, int out_size)
{
    const float* x        = (const float*)d_in[0];
    const int*   duration = (const int*)  d_in[2];
    const float* pitch_t  = (const float*)d_in[3];
    const float* energy_t = (const float*)d_in[4];
    const float* c1w = (const float*)d_in[5];
    const float* c1b = (const float*)d_in[6];
    const float* g1  = (const float*)d_in[7];
    const float* b1  = (const float*)d_in[8];
    const float* c2w = (const float*)d_in[9];
    const float* c2b = (const float*)d_in[10];
    const float* g2  = (const float*)d_in[11];
    const float* b2  = (const float*)d_in[12];
    const float* lw  = (const float*)d_in[13];
    const float* lb  = (const float*)d_in[14];
    const float* pbins = (const float*)d_in[15];
    const float* ebins = (const float*)d_in[16];
    const float* ptab  = (const float*)d_in[17];
    const float* etab  = (const float*)d_in[18];

    float* out = (float*)d_out;
    const size_t OFF_LOGDUR = (size_t)B_ * MAXL * H_;
    const size_t OFF_MELLEN = OFF_LOGDUR + 3 * (size_t)B_ * T_;
    const size_t OFF_MASK   = OFF_MELLEN + B_;

    uint32_t *p_xp, *p_x2p, *p_h1p, *p_w1p, *p_w2p, *p_h2;
    float *p_x3;
    int *p_cum, *p_ml;
    cudaGetSymbolAddress((void**)&p_xp,  g_xp);
    cudaGetSymbolAddress((void**)&p_x2p, g_x2p);
    cudaGetSymbolAddress((void**)&p_h1p, g_h1p);
    cudaGetSymbolAddress((void**)&p_w1p, g_w1p);
    cudaGetSymbolAddress((void**)&p_w2p, g_w2p);
    cudaGetSymbolAddress((void**)&p_h2,  g_h2);
    cudaGetSymbolAddress((void**)&p_x3,  g_x3);
    cudaGetSymbolAddress((void**)&p_cum, g_cum);
    cudaGetSymbolAddress((void**)&p_ml,  g_ml);

    cudaFuncSetAttribute(conv_fp16_kernel,
                         cudaFuncAttributeMaxDynamicSharedMemorySize, CONV_SMEM);

    cudaStream_t s1, s2;
    cudaStreamCreateWithFlags(&s1, cudaStreamNonBlocking);
    cudaStreamCreateWithFlags(&s2, cudaStreamNonBlocking);
    cudaEvent_t evStart, evPrep, evS1, evW2, evExpand;
    cudaEventCreateWithFlags(&evStart,  cudaEventDisableTiming);
    cudaEventCreateWithFlags(&evPrep,   cudaEventDisableTiming);
    cudaEventCreateWithFlags(&evS1,     cudaEventDisableTiming);
    cudaEventCreateWithFlags(&evW2,     cudaEventDisableTiming);
    cudaEventCreateWithFlags(&evExpand, cudaEventDisableTiming);

    // ---- root fork ----
    cudaEventRecord(evStart, 0);
    cudaStreamWaitEvent(s1, evStart, 0);
    cudaStreamWaitEvent(s2, evStart, 0);

    // s1: conv1 prerequisites (halo/counter zero + w1 pack)
    zero_halo_kernel<<<363, 256, 0, s1>>>(p_xp, p_x2p, p_h1p);
    pack_w_kernel<<<WP_W / 256, 256, 0, s1>>>(c1w, p_w1p);
    cudaEventRecord(evS1, s1);

    // s2: cumsum (gates expand) + w2 pack (gates conv2 only)
    cumsum_kernel<<<B_, 512, 0, s2>>>(duration, p_cum, p_ml, out + OFF_MELLEN);
    pack_w_kernel<<<WP_W / 256, 256, 0, s2>>>(c2w, p_w2p);
    cudaEventRecord(evW2, s2);

    // main: prep_x only
    prep_x_kernel<<<B_ * T_, 128>>>(x, pitch_t, energy_t, pbins, ebins,
                                    ptab, etab, p_xp, p_x2p, p_x3);
    cudaEventRecord(evPrep, 0);

    // s2: expand under conv1 (needs prep_x + cumsum)
    cudaStreamWaitEvent(s2, evPrep, 0);
    dim3 egrid(MAXL, B_);
    expand_kernel<<<egrid, 128, 0, s2>>>(p_x3, p_cum, p_ml, out, out + OFF_MASK);
    cudaEventRecord(evExpand, s2);

    // main: conv chain with fused LN epilogues
    cudaStreamWaitEvent(0, evS1, 0);
    dim3 cgrid(4, 4, 96);
    conv_fp16_kernel<<<cgrid, 256, CONV_SMEM>>>(
        p_xp, p_xp, p_x2p, p_w1p, c1b, p_h1p, 1,
        g1, b1, nullptr, nullptr, nullptr);
    cudaStreamWaitEvent(0, evW2, 0);
    conv_fp16_kernel<<<cgrid, 256, CONV_SMEM>>>(
        p_h1p, p_h1p + PSTR_W, p_h1p + 2 * (size_t)PSTR_W, p_w2p, c2b, p_h2, 0,
        g2, b2, lw, lb, out + OFF_LOGDUR);

    // join
    cudaStreamWaitEvent(0, evExpand, 0);

    cudaEventDestroy(evStart);
    cudaEventDestroy(evPrep);
    cudaEventDestroy(evS1);
    cudaEventDestroy(evW2);
    cudaEventDestroy(evExpand);
    cudaStreamDestroy(s1);
    cudaStreamDestroy(s2);
}